// round 9
// baseline (speedup 1.0000x reference)
#include <cuda_runtime.h>
#include <cstddef>

#define Bb 64
#define Tt 2048
#define Hh 512
#define Pp 256
#define CHUNKS 4
#define LOG2E 1.4426950408889634f

// ---- device scratch ----
__device__ float g_qpart[Bb * 8 * Pp];
__device__ float g_kq[Bb * Hh];
__device__ float g_bkq[Bb];
__device__ float g_raw[Bb * Tt];
__device__ float g_pz[Bb * CHUNKS];
__device__ float g_pacc[(size_t)Bb * CHUNKS * Hh];
__device__ float g_cpart[Bb * 8 * Pp];

__device__ __forceinline__ float fexp2(float x) {
    float y;
    asm("ex2.approx.f32 %0, %1;" : "=f"(y) : "f"(x));
    return y;
}

__device__ __forceinline__ float dot16(const float4 v0, const float4 v1,
                                       const float4 v2, const float4 v3,
                                       const float4 k0, const float4 k1,
                                       const float4 k2, const float4 k3)
{
    float p0 = fmaf(v0.y, k0.y, v0.x * k0.x);
    float p1 = fmaf(v0.w, k0.w, v0.z * k0.z);
    float p2 = fmaf(v1.y, k1.y, v1.x * k1.x);
    float p3 = fmaf(v1.w, k1.w, v1.z * k1.z);
    float p4 = fmaf(v2.y, k2.y, v2.x * k2.x);
    float p5 = fmaf(v2.w, k2.w, v2.z * k2.z);
    float p6 = fmaf(v3.y, k3.y, v3.x * k3.x);
    float p7 = fmaf(v3.w, k3.w, v3.z * k3.z);
    return ((p0 + p1) + (p2 + p3)) + ((p4 + p5) + (p6 + p7));
}

// ---------------------------------------------------------------------------
// K1: q partials. grid (8 e-chunks, 64 b) x 256.
// ---------------------------------------------------------------------------
__global__ __launch_bounds__(256) void k_qpart(
    const float* __restrict__ dec, const float* __restrict__ Wq)
{
    __shared__ float sdec[64];
    const int ec = blockIdx.x, b = blockIdx.y, p = threadIdx.x;
    const int e0 = ec * 64;

    if (p < 64) sdec[p] = dec[b * Hh + e0 + p];
    __syncthreads();

    float a0 = 0.f, a1 = 0.f, a2 = 0.f, a3 = 0.f;
#pragma unroll
    for (int j0 = 0; j0 < 64; j0 += 16) {
        float w[16];
#pragma unroll
        for (int j = 0; j < 16; j++) w[j] = Wq[(e0 + j0 + j) * Pp + p];
#pragma unroll
        for (int j = 0; j < 16; j += 4) {
            a0 = fmaf(sdec[j0 + j + 0], w[j + 0], a0);
            a1 = fmaf(sdec[j0 + j + 1], w[j + 1], a1);
            a2 = fmaf(sdec[j0 + j + 2], w[j + 2], a2);
            a3 = fmaf(sdec[j0 + j + 3], w[j + 3], a3);
        }
    }
    g_qpart[(b * 8 + ec) * Pp + p] = (a0 + a1) + (a2 + a3);
}

// ---------------------------------------------------------------------------
// K2 (fused): sum q partials (+bq) in smem, compute bkq (block x==0 only),
// then kq[b,e] = Wk[e,:] . q.  grid (4 e-chunks, 64 b) x 128, thread = e.
// ---------------------------------------------------------------------------
__global__ __launch_bounds__(128) void k_kq(
    const float* __restrict__ Wk, const float* __restrict__ bq,
    const float* __restrict__ bk)
{
    __shared__ float sq[Pp];
    __shared__ float sred[4];
    const int b = blockIdx.y, tid = threadIdx.x;
    const int e = blockIdx.x * 128 + tid;

#pragma unroll
    for (int h = 0; h < 2; h++) {
        const int p = tid + h * 128;
        float s = bq[p];
#pragma unroll
        for (int c = 0; c < 8; c++) s += g_qpart[(b * 8 + c) * Pp + p];
        sq[p] = s;
    }
    __syncthreads();

    if (blockIdx.x == 0) {
        float r = bk[tid] * sq[tid] + bk[tid + 128] * sq[tid + 128];
#pragma unroll
        for (int o = 16; o; o >>= 1) r += __shfl_xor_sync(0xffffffffu, r, o);
        if ((tid & 31) == 0) sred[tid >> 5] = r;
    }
    __syncthreads();
    if (blockIdx.x == 0 && tid == 0)
        g_bkq[b] = (sred[0] + sred[1]) + (sred[2] + sred[3]);

    const float4* w4 = (const float4*)(Wk + (size_t)e * Pp);
    float a0 = 0.f, a1 = 0.f, a2 = 0.f, a3 = 0.f;
#pragma unroll
    for (int p4 = 0; p4 < Pp / 4; p4 += 8) {
        float4 w[8];
#pragma unroll
        for (int j = 0; j < 8; j++) w[j] = w4[p4 + j];
#pragma unroll
        for (int j = 0; j < 8; j++) {
            a0 = fmaf(w[j].x, sq[4 * (p4 + j) + 0], a0);
            a1 = fmaf(w[j].y, sq[4 * (p4 + j) + 1], a1);
            a2 = fmaf(w[j].z, sq[4 * (p4 + j) + 2], a2);
            a3 = fmaf(w[j].w, sq[4 * (p4 + j) + 3], a3);
        }
    }
    g_kq[b * Hh + e] = (a0 + a1) + (a2 + a3);
}

// ---------------------------------------------------------------------------
// K3: streaming pass (256 MB). 256 CTAs, 3 CTAs/SM (leaner register body):
// single-row mainloop with explicit next-row register prefetch.
// Flat-exp softmax, CTA-level smem partial reduction.
// ---------------------------------------------------------------------------
__global__ __launch_bounds__(256, 3) void k_stream(const float* __restrict__ enc)
{
    __shared__ float sacc[8][Hh];
    __shared__ float sZ[8];

    const int lane = threadIdx.x & 31;
    const int warp = threadIdx.x >> 5;
    const int b     = blockIdx.x >> 2;
    const int chunk = blockIdx.x & 3;
    const int t0    = chunk * (Tt / CHUNKS) + warp * 64;

    const float4* kq4 = (const float4*)(g_kq + (size_t)b * Hh);
    const float4 k0 = kq4[lane], k1 = kq4[32 + lane],
                 k2 = kq4[64 + lane], k3 = kq4[96 + lane];
    const float bkq = g_bkq[b];

    float4 a0 = {0.f, 0.f, 0.f, 0.f}, a1 = a0, a2 = a0, a3 = a0;
    float Z = 0.f, myS = 0.f;

    const float4* base = (const float4*)(enc + ((size_t)b * Tt + t0) * Hh);
    float4 n0 = base[lane], n1 = base[32 + lane],
           n2 = base[64 + lane], n3 = base[96 + lane];

#pragma unroll 2
    for (int i = 0; i < 64; i++) {
        const float4 v0 = n0, v1 = n1, v2 = n2, v3 = n3;
        if (i < 63) {
            const float4* r = base + (size_t)(i + 1) * (Hh / 4);
            n0 = r[lane]; n1 = r[32 + lane];
            n2 = r[64 + lane]; n3 = r[96 + lane];
        }

        float d = dot16(v0, v1, v2, v3, k0, k1, k2, k3);
        d += __shfl_xor_sync(0xffffffffu, d, 16);
        d += __shfl_xor_sync(0xffffffffu, d, 8);
        d += __shfl_xor_sync(0xffffffffu, d, 4);
        d += __shfl_xor_sync(0xffffffffu, d, 2);
        d += __shfl_xor_sync(0xffffffffu, d, 1);

        const float s = d + bkq;
        if (lane == (i & 31)) myS = s;

        const float w = fexp2(s * LOG2E);
        Z += w;
        a0.x = fmaf(w, v0.x, a0.x); a0.y = fmaf(w, v0.y, a0.y);
        a0.z = fmaf(w, v0.z, a0.z); a0.w = fmaf(w, v0.w, a0.w);
        a1.x = fmaf(w, v1.x, a1.x); a1.y = fmaf(w, v1.y, a1.y);
        a1.z = fmaf(w, v1.z, a1.z); a1.w = fmaf(w, v1.w, a1.w);
        a2.x = fmaf(w, v2.x, a2.x); a2.y = fmaf(w, v2.y, a2.y);
        a2.z = fmaf(w, v2.z, a2.z); a2.w = fmaf(w, v2.w, a2.w);
        a3.x = fmaf(w, v3.x, a3.x); a3.y = fmaf(w, v3.y, a3.y);
        a3.z = fmaf(w, v3.z, a3.z); a3.w = fmaf(w, v3.w, a3.w);

        if ((i & 31) == 31)
            g_raw[b * Tt + t0 + (i & 32) + lane] = myS;
    }

    // CTA reduction (partials purely additive under flat exp)
    float4* sa = (float4*)sacc[warp];
    sa[lane] = a0; sa[32 + lane] = a1; sa[64 + lane] = a2; sa[96 + lane] = a3;
    if (lane == 0) sZ[warp] = Z;
    __syncthreads();

    const int pid = blockIdx.x;
    if (threadIdx.x < 128) {
        float4 s = {0.f, 0.f, 0.f, 0.f};
#pragma unroll
        for (int w = 0; w < 8; w++) {
            float4 v = ((const float4*)sacc[w])[threadIdx.x];
            s.x += v.x; s.y += v.y; s.z += v.z; s.w += v.w;
        }
        ((float4*)(g_pacc + (size_t)pid * Hh))[threadIdx.x] = s;
    } else if (threadIdx.x == 128) {
        float z = 0.f;
#pragma unroll
        for (int w = 0; w < 8; w++) z += sZ[w];
        g_pz[pid] = z;
    }
}

// ---------------------------------------------------------------------------
// K4 (fused): attn segment + ctx@Wv partial. grid (8 e-chunks, 64 b) x 256.
// Segment ec covers attn t in [ec*256, ec*256+256).
// ---------------------------------------------------------------------------
__global__ __launch_bounds__(256) void k_cpart(
    const float* __restrict__ Wv, float* __restrict__ out)
{
    __shared__ float ssctx[64];
    const int ec = blockIdx.x, b = blockIdx.y, p = threadIdx.x;
    const int e0 = ec * 64;

    float Z = 0.f;
#pragma unroll
    for (int i = 0; i < CHUNKS; i++) Z += g_pz[b * CHUNKS + i];
    const float invZ = 1.f / Z;

    // attn epilogue for this 256-t segment
    const int t = ec * 256 + p;
    out[Bb * Pp + b * Tt + t] = fexp2(g_raw[b * Tt + t] * LOG2E) * invZ;

    if (p < 64) {
        const int e = e0 + p;
        float s = 0.f;
#pragma unroll
        for (int c = 0; c < CHUNKS; c++)
            s += g_pacc[(size_t)(b * CHUNKS + c) * Hh + e];
        ssctx[p] = s * invZ;
    }
    __syncthreads();

    float a0 = 0.f, a1 = 0.f, a2 = 0.f, a3 = 0.f;
#pragma unroll
    for (int j0 = 0; j0 < 64; j0 += 16) {
        float w[16];
#pragma unroll
        for (int j = 0; j < 16; j++) w[j] = Wv[(e0 + j0 + j) * Pp + p];
#pragma unroll
        for (int j = 0; j < 16; j += 4) {
            a0 = fmaf(ssctx[j0 + j + 0], w[j + 0], a0);
            a1 = fmaf(ssctx[j0 + j + 1], w[j + 1], a1);
            a2 = fmaf(ssctx[j0 + j + 2], w[j + 2], a2);
            a3 = fmaf(ssctx[j0 + j + 3], w[j + 3], a3);
        }
    }
    g_cpart[(b * 8 + ec) * Pp + p] = (a0 + a1) + (a2 + a3);
}

// ---------------------------------------------------------------------------
// K5: context = sum partials + bv.  grid 64 x 256.
// ---------------------------------------------------------------------------
__global__ __launch_bounds__(256) void k_csum(
    const float* __restrict__ bv, float* __restrict__ out)
{
    const int b = blockIdx.x, p = threadIdx.x;
    float c = bv[p];
#pragma unroll
    for (int i = 0; i < 8; i++) c += g_cpart[(b * 8 + i) * Pp + p];
    out[b * Pp + p] = c;
}

// ---------------------------------------------------------------------------
extern "C" void kernel_launch(void* const* d_in, const int* in_sizes, int n_in,
                              void* d_out, int out_size)
{
    const float* dec = (const float*)d_in[0];
    const float* enc = (const float*)d_in[1];
    const float* Wk  = (const float*)d_in[3];
    const float* bk  = (const float*)d_in[4];
    const float* Wv  = (const float*)d_in[5];
    const float* bv  = (const float*)d_in[6];
    const float* Wq  = (const float*)d_in[7];
    const float* bq  = (const float*)d_in[8];
    float* out = (float*)d_out;

    k_qpart<<<dim3(8, Bb), 256>>>(dec, Wq);
    k_kq<<<dim3(4, Bb), 128>>>(Wk, bq, bk);
    k_stream<<<Bb * CHUNKS, 256>>>(enc);
    k_cpart<<<dim3(8, Bb), 256>>>(Wv, out);
    k_csum<<<Bb, 256>>>(bv, out);
}

// round 11
// speedup vs baseline: 1.1058x; 1.1058x over previous
#include <cuda_runtime.h>
#include <cstddef>

#define Bb 64
#define Tt 2048
#define Hh 512
#define Pp 256
#define CHUNKS 4
#define LOG2E 1.4426950408889634f

// ---- device scratch ----
__device__ float g_qpart[Bb * 8 * Pp];
__device__ float g_kq[Bb * Hh];
__device__ float g_bkq[Bb];
__device__ float g_raw[Bb * Tt];
__device__ float g_pz[Bb * CHUNKS];
__device__ float g_pacc[(size_t)Bb * CHUNKS * Hh];
__device__ float g_cpart[Bb * 8 * Pp];

__device__ __forceinline__ float fexp2(float x) {
    float y;
    asm("ex2.approx.f32 %0, %1;" : "=f"(y) : "f"(x));
    return y;
}

__device__ __forceinline__ float dot16(const float4 v0, const float4 v1,
                                       const float4 v2, const float4 v3,
                                       const float4 k0, const float4 k1,
                                       const float4 k2, const float4 k3)
{
    float p0 = fmaf(v0.y, k0.y, v0.x * k0.x);
    float p1 = fmaf(v0.w, k0.w, v0.z * k0.z);
    float p2 = fmaf(v1.y, k1.y, v1.x * k1.x);
    float p3 = fmaf(v1.w, k1.w, v1.z * k1.z);
    float p4 = fmaf(v2.y, k2.y, v2.x * k2.x);
    float p5 = fmaf(v2.w, k2.w, v2.z * k2.z);
    float p6 = fmaf(v3.y, k3.y, v3.x * k3.x);
    float p7 = fmaf(v3.w, k3.w, v3.z * k3.z);
    return ((p0 + p1) + (p2 + p3)) + ((p4 + p5) + (p6 + p7));
}

// ---------------------------------------------------------------------------
// K1: q partials. grid (8 e-chunks, 64 b) x 256.
// ---------------------------------------------------------------------------
__global__ __launch_bounds__(256) void k_qpart(
    const float* __restrict__ dec, const float* __restrict__ Wq)
{
    __shared__ float sdec[64];
    const int ec = blockIdx.x, b = blockIdx.y, p = threadIdx.x;
    const int e0 = ec * 64;

    if (p < 64) sdec[p] = dec[b * Hh + e0 + p];
    __syncthreads();

    float a0 = 0.f, a1 = 0.f, a2 = 0.f, a3 = 0.f;
#pragma unroll
    for (int j0 = 0; j0 < 64; j0 += 16) {
        float w[16];
#pragma unroll
        for (int j = 0; j < 16; j++) w[j] = Wq[(e0 + j0 + j) * Pp + p];
#pragma unroll
        for (int j = 0; j < 16; j += 4) {
            a0 = fmaf(sdec[j0 + j + 0], w[j + 0], a0);
            a1 = fmaf(sdec[j0 + j + 1], w[j + 1], a1);
            a2 = fmaf(sdec[j0 + j + 2], w[j + 2], a2);
            a3 = fmaf(sdec[j0 + j + 3], w[j + 3], a3);
        }
    }
    g_qpart[(b * 8 + ec) * Pp + p] = (a0 + a1) + (a2 + a3);
}

// ---------------------------------------------------------------------------
// K2 (fused): sum q partials (+bq), bkq on block x==0, then kq GEMV.
// grid (4 e-chunks, 64 b) x 128, thread = e.
// ---------------------------------------------------------------------------
__global__ __launch_bounds__(128) void k_kq(
    const float* __restrict__ Wk, const float* __restrict__ bq,
    const float* __restrict__ bk)
{
    __shared__ float sq[Pp];
    __shared__ float sred[4];
    const int b = blockIdx.y, tid = threadIdx.x;
    const int e = blockIdx.x * 128 + tid;

#pragma unroll
    for (int h = 0; h < 2; h++) {
        const int p = tid + h * 128;
        float s = bq[p];
#pragma unroll
        for (int c = 0; c < 8; c++) s += g_qpart[(b * 8 + c) * Pp + p];
        sq[p] = s;
    }
    __syncthreads();

    if (blockIdx.x == 0) {
        float r = bk[tid] * sq[tid] + bk[tid + 128] * sq[tid + 128];
#pragma unroll
        for (int o = 16; o; o >>= 1) r += __shfl_xor_sync(0xffffffffu, r, o);
        if ((tid & 31) == 0) sred[tid >> 5] = r;
    }
    __syncthreads();
    if (blockIdx.x == 0 && tid == 0)
        g_bkq[b] = (sred[0] + sred[1]) + (sred[2] + sred[3]);

    const float4* w4 = (const float4*)(Wk + (size_t)e * Pp);
    float a0 = 0.f, a1 = 0.f, a2 = 0.f, a3 = 0.f;
#pragma unroll
    for (int p4 = 0; p4 < Pp / 4; p4 += 8) {
        float4 w[8];
#pragma unroll
        for (int j = 0; j < 8; j++) w[j] = w4[p4 + j];
#pragma unroll
        for (int j = 0; j < 8; j++) {
            a0 = fmaf(w[j].x, sq[4 * (p4 + j) + 0], a0);
            a1 = fmaf(w[j].y, sq[4 * (p4 + j) + 1], a1);
            a2 = fmaf(w[j].z, sq[4 * (p4 + j) + 2], a2);
            a3 = fmaf(w[j].w, sq[4 * (p4 + j) + 3], a3);
        }
    }
    g_kq[b * Hh + e] = (a0 + a1) + (a2 + a3);
}

// ---------------------------------------------------------------------------
// K3: streaming pass (256 MB). 256 CTAs @ 2/SM. FOUR rows per body:
// 16 front-batched LDG.128, 4 independent dot trees, 20 fully-interleaved
// shuffles (4 pipelined chains), flat-exp softmax, 4-deep fused accumulate.
// ---------------------------------------------------------------------------
__global__ __launch_bounds__(256, 2) void k_stream(const float* __restrict__ enc)
{
    __shared__ float sacc[8][Hh];
    __shared__ float sZ[8];

    const int lane = threadIdx.x & 31;
    const int warp = threadIdx.x >> 5;
    const int b     = blockIdx.x >> 2;
    const int chunk = blockIdx.x & 3;
    const int t0    = chunk * (Tt / CHUNKS) + warp * 64;

    const float4* kq4 = (const float4*)(g_kq + (size_t)b * Hh);
    const float4 k0 = kq4[lane], k1 = kq4[32 + lane],
                 k2 = kq4[64 + lane], k3 = kq4[96 + lane];
    const float bkq = g_bkq[b];

    float4 a0 = {0.f, 0.f, 0.f, 0.f}, a1 = a0, a2 = a0, a3 = a0;
    float Z = 0.f;

#pragma unroll
    for (int grp = 0; grp < 2; grp++) {
        const float4* base =
            (const float4*)(enc + ((size_t)b * Tt + t0 + grp * 32) * Hh);
        float myS = 0.f;

#pragma unroll 1
        for (int i = 0; i < 8; i++) {      // 4 rows per iteration
            const float4* rA = base + (size_t)(4 * i)     * (Hh / 4);
            const float4* rB = base + (size_t)(4 * i + 1) * (Hh / 4);
            const float4* rC = base + (size_t)(4 * i + 2) * (Hh / 4);
            const float4* rD = base + (size_t)(4 * i + 3) * (Hh / 4);
            float4 uA0 = rA[lane], uA1 = rA[32 + lane],
                   uA2 = rA[64 + lane], uA3 = rA[96 + lane];
            float4 uB0 = rB[lane], uB1 = rB[32 + lane],
                   uB2 = rB[64 + lane], uB3 = rB[96 + lane];
            float4 uC0 = rC[lane], uC1 = rC[32 + lane],
                   uC2 = rC[64 + lane], uC3 = rC[96 + lane];
            float4 uD0 = rD[lane], uD1 = rD[32 + lane],
                   uD2 = rD[64 + lane], uD3 = rD[96 + lane];

            float dA = dot16(uA0, uA1, uA2, uA3, k0, k1, k2, k3);
            float dB = dot16(uB0, uB1, uB2, uB3, k0, k1, k2, k3);
            float dC = dot16(uC0, uC1, uC2, uC3, k0, k1, k2, k3);
            float dD = dot16(uD0, uD1, uD2, uD3, k0, k1, k2, k3);

            dA += __shfl_xor_sync(0xffffffffu, dA, 16);
            dB += __shfl_xor_sync(0xffffffffu, dB, 16);
            dC += __shfl_xor_sync(0xffffffffu, dC, 16);
            dD += __shfl_xor_sync(0xffffffffu, dD, 16);
            dA += __shfl_xor_sync(0xffffffffu, dA, 8);
            dB += __shfl_xor_sync(0xffffffffu, dB, 8);
            dC += __shfl_xor_sync(0xffffffffu, dC, 8);
            dD += __shfl_xor_sync(0xffffffffu, dD, 8);
            dA += __shfl_xor_sync(0xffffffffu, dA, 4);
            dB += __shfl_xor_sync(0xffffffffu, dB, 4);
            dC += __shfl_xor_sync(0xffffffffu, dC, 4);
            dD += __shfl_xor_sync(0xffffffffu, dD, 4);
            dA += __shfl_xor_sync(0xffffffffu, dA, 2);
            dB += __shfl_xor_sync(0xffffffffu, dB, 2);
            dC += __shfl_xor_sync(0xffffffffu, dC, 2);
            dD += __shfl_xor_sync(0xffffffffu, dD, 2);
            dA += __shfl_xor_sync(0xffffffffu, dA, 1);
            dB += __shfl_xor_sync(0xffffffffu, dB, 1);
            dC += __shfl_xor_sync(0xffffffffu, dC, 1);
            dD += __shfl_xor_sync(0xffffffffu, dD, 1);

            const float sA = dA + bkq, sB = dB + bkq;
            const float sC = dC + bkq, sD = dD + bkq;
            if (lane == 4 * i)     myS = sA;
            if (lane == 4 * i + 1) myS = sB;
            if (lane == 4 * i + 2) myS = sC;
            if (lane == 4 * i + 3) myS = sD;

            const float wA = fexp2(sA * LOG2E), wB = fexp2(sB * LOG2E);
            const float wC = fexp2(sC * LOG2E), wD = fexp2(sD * LOG2E);
            Z += (wA + wB) + (wC + wD);

            a0.x = fmaf(wA, uA0.x, fmaf(wB, uB0.x, fmaf(wC, uC0.x, fmaf(wD, uD0.x, a0.x))));
            a0.y = fmaf(wA, uA0.y, fmaf(wB, uB0.y, fmaf(wC, uC0.y, fmaf(wD, uD0.y, a0.y))));
            a0.z = fmaf(wA, uA0.z, fmaf(wB, uB0.z, fmaf(wC, uC0.z, fmaf(wD, uD0.z, a0.z))));
            a0.w = fmaf(wA, uA0.w, fmaf(wB, uB0.w, fmaf(wC, uC0.w, fmaf(wD, uD0.w, a0.w))));
            a1.x = fmaf(wA, uA1.x, fmaf(wB, uB1.x, fmaf(wC, uC1.x, fmaf(wD, uD1.x, a1.x))));
            a1.y = fmaf(wA, uA1.y, fmaf(wB, uB1.y, fmaf(wC, uC1.y, fmaf(wD, uD1.y, a1.y))));
            a1.z = fmaf(wA, uA1.z, fmaf(wB, uB1.z, fmaf(wC, uC1.z, fmaf(wD, uD1.z, a1.z))));
            a1.w = fmaf(wA, uA1.w, fmaf(wB, uB1.w, fmaf(wC, uC1.w, fmaf(wD, uD1.w, a1.w))));
            a2.x = fmaf(wA, uA2.x, fmaf(wB, uB2.x, fmaf(wC, uC2.x, fmaf(wD, uD2.x, a2.x))));
            a2.y = fmaf(wA, uA2.y, fmaf(wB, uB2.y, fmaf(wC, uC2.y, fmaf(wD, uD2.y, a2.y))));
            a2.z = fmaf(wA, uA2.z, fmaf(wB, uB2.z, fmaf(wC, uC2.z, fmaf(wD, uD2.z, a2.z))));
            a2.w = fmaf(wA, uA2.w, fmaf(wB, uB2.w, fmaf(wC, uC2.w, fmaf(wD, uD2.w, a2.w))));
            a3.x = fmaf(wA, uA3.x, fmaf(wB, uB3.x, fmaf(wC, uC3.x, fmaf(wD, uD3.x, a3.x))));
            a3.y = fmaf(wA, uA3.y, fmaf(wB, uB3.y, fmaf(wC, uC3.y, fmaf(wD, uD3.y, a3.y))));
            a3.z = fmaf(wA, uA3.z, fmaf(wB, uB3.z, fmaf(wC, uC3.z, fmaf(wD, uD3.z, a3.z))));
            a3.w = fmaf(wA, uA3.w, fmaf(wB, uB3.w, fmaf(wC, uC3.w, fmaf(wD, uD3.w, a3.w))));
        }
        g_raw[b * Tt + t0 + grp * 32 + lane] = myS;
    }

    // CTA reduction (partials purely additive under flat exp)
    float4* sa = (float4*)sacc[warp];
    sa[lane] = a0; sa[32 + lane] = a1; sa[64 + lane] = a2; sa[96 + lane] = a3;
    if (lane == 0) sZ[warp] = Z;
    __syncthreads();

    const int pid = blockIdx.x;
    if (threadIdx.x < 128) {
        float4 s = {0.f, 0.f, 0.f, 0.f};
#pragma unroll
        for (int w = 0; w < 8; w++) {
            float4 v = ((const float4*)sacc[w])[threadIdx.x];
            s.x += v.x; s.y += v.y; s.z += v.z; s.w += v.w;
        }
        ((float4*)(g_pacc + (size_t)pid * Hh))[threadIdx.x] = s;
    } else if (threadIdx.x == 128) {
        float z = 0.f;
#pragma unroll
        for (int w = 0; w < 8; w++) z += sZ[w];
        g_pz[pid] = z;
    }
}

// ---------------------------------------------------------------------------
// K4 (fused): attn segment + ctx@Wv partial. grid (8 e-chunks, 64 b) x 256.
// ---------------------------------------------------------------------------
__global__ __launch_bounds__(256) void k_cpart(
    const float* __restrict__ Wv, float* __restrict__ out)
{
    __shared__ float ssctx[64];
    const int ec = blockIdx.x, b = blockIdx.y, p = threadIdx.x;
    const int e0 = ec * 64;

    float Z = 0.f;
#pragma unroll
    for (int i = 0; i < CHUNKS; i++) Z += g_pz[b * CHUNKS + i];
    const float invZ = 1.f / Z;

    const int t = ec * 256 + p;
    out[Bb * Pp + b * Tt + t] = fexp2(g_raw[b * Tt + t] * LOG2E) * invZ;

    if (p < 64) {
        const int e = e0 + p;
        float s = 0.f;
#pragma unroll
        for (int c = 0; c < CHUNKS; c++)
            s += g_pacc[(size_t)(b * CHUNKS + c) * Hh + e];
        ssctx[p] = s * invZ;
    }
    __syncthreads();

    float a0 = 0.f, a1 = 0.f, a2 = 0.f, a3 = 0.f;
#pragma unroll
    for (int j0 = 0; j0 < 64; j0 += 16) {
        float w[16];
#pragma unroll
        for (int j = 0; j < 16; j++) w[j] = Wv[(e0 + j0 + j) * Pp + p];
#pragma unroll
        for (int j = 0; j < 16; j += 4) {
            a0 = fmaf(ssctx[j0 + j + 0], w[j + 0], a0);
            a1 = fmaf(ssctx[j0 + j + 1], w[j + 1], a1);
            a2 = fmaf(ssctx[j0 + j + 2], w[j + 2], a2);
            a3 = fmaf(ssctx[j0 + j + 3], w[j + 3], a3);
        }
    }
    g_cpart[(b * 8 + ec) * Pp + p] = (a0 + a1) + (a2 + a3);
}

// ---------------------------------------------------------------------------
// K5: context = sum partials + bv.  grid 64 x 256.
// ---------------------------------------------------------------------------
__global__ __launch_bounds__(256) void k_csum(
    const float* __restrict__ bv, float* __restrict__ out)
{
    const int b = blockIdx.x, p = threadIdx.x;
    float c = bv[p];
#pragma unroll
    for (int i = 0; i < 8; i++) c += g_cpart[(b * 8 + i) * Pp + p];
    out[b * Pp + p] = c;
}

// ---------------------------------------------------------------------------
extern "C" void kernel_launch(void* const* d_in, const int* in_sizes, int n_in,
                              void* d_out, int out_size)
{
    const float* dec = (const float*)d_in[0];
    const float* enc = (const float*)d_in[1];
    const float* Wk  = (const float*)d_in[3];
    const float* bk  = (const float*)d_in[4];
    const float* Wv  = (const float*)d_in[5];
    const float* bv  = (const float*)d_in[6];
    const float* Wq  = (const float*)d_in[7];
    const float* bq  = (const float*)d_in[8];
    float* out = (float*)d_out;

    k_qpart<<<dim3(8, Bb), 256>>>(dec, Wq);
    k_kq<<<dim3(4, Bb), 128>>>(Wk, bq, bk);
    k_stream<<<Bb * CHUNKS, 256>>>(enc);
    k_cpart<<<dim3(8, Bb), 256>>>(Wv, out);
    k_csum<<<Bb, 256>>>(bv, out);
}

// round 13
// speedup vs baseline: 1.1096x; 1.0035x over previous
#include <cuda_runtime.h>
#include <cstddef>

#define Bb 64
#define Tt 2048
#define Hh 512
#define Pp 256
#define CHUNKS 4
#define ECH 16            // e-chunks for the partial GEMVs
#define LOG2E 1.4426950408889634f

// ---- device scratch ----
__device__ float g_qpart[Bb * ECH * Pp];               // 1 MB
__device__ float g_kq[Bb * Hh];
__device__ float g_bkq[Bb];
__device__ float g_raw[Bb * Tt];
__device__ float g_pz[Bb * CHUNKS];
__device__ float g_pacc[(size_t)Bb * CHUNKS * Hh];
__device__ float g_cpart[Bb * ECH * Pp];               // 1 MB

__device__ __forceinline__ float fexp2(float x) {
    float y;
    asm("ex2.approx.f32 %0, %1;" : "=f"(y) : "f"(x));
    return y;
}

__device__ __forceinline__ float dot16(const float4 v0, const float4 v1,
                                       const float4 v2, const float4 v3,
                                       const float4 k0, const float4 k1,
                                       const float4 k2, const float4 k3)
{
    float p0 = fmaf(v0.y, k0.y, v0.x * k0.x);
    float p1 = fmaf(v0.w, k0.w, v0.z * k0.z);
    float p2 = fmaf(v1.y, k1.y, v1.x * k1.x);
    float p3 = fmaf(v1.w, k1.w, v1.z * k1.z);
    float p4 = fmaf(v2.y, k2.y, v2.x * k2.x);
    float p5 = fmaf(v2.w, k2.w, v2.z * k2.z);
    float p6 = fmaf(v3.y, k3.y, v3.x * k3.x);
    float p7 = fmaf(v3.w, k3.w, v3.z * k3.z);
    return ((p0 + p1) + (p2 + p3)) + ((p4 + p5) + (p6 + p7));
}

// ---------------------------------------------------------------------------
// K1: q partials. grid (16 e-chunks, 64 b) x 256. 32-term dots (2 batches).
// ---------------------------------------------------------------------------
__global__ __launch_bounds__(256) void k_qpart(
    const float* __restrict__ dec, const float* __restrict__ Wq)
{
    __shared__ float sdec[32];
    const int ec = blockIdx.x, b = blockIdx.y, p = threadIdx.x;
    const int e0 = ec * 32;

    if (p < 32) sdec[p] = dec[b * Hh + e0 + p];
    __syncthreads();

    float a0 = 0.f, a1 = 0.f, a2 = 0.f, a3 = 0.f;
#pragma unroll
    for (int j0 = 0; j0 < 32; j0 += 16) {
        float w[16];
#pragma unroll
        for (int j = 0; j < 16; j++) w[j] = Wq[(e0 + j0 + j) * Pp + p];
#pragma unroll
        for (int j = 0; j < 16; j += 4) {
            a0 = fmaf(sdec[j0 + j + 0], w[j + 0], a0);
            a1 = fmaf(sdec[j0 + j + 1], w[j + 1], a1);
            a2 = fmaf(sdec[j0 + j + 2], w[j + 2], a2);
            a3 = fmaf(sdec[j0 + j + 3], w[j + 3], a3);
        }
    }
    g_qpart[(b * ECH + ec) * Pp + p] = (a0 + a1) + (a2 + a3);
}

// ---------------------------------------------------------------------------
// K2 (fused): sum q partials (+bq) -> sq, bkq on block x==0, then kq GEMV
// with TWO threads per output e (each half of the p-range) + smem combine.
// grid (4 e-chunks, 64 b) x 256.
// ---------------------------------------------------------------------------
__global__ __launch_bounds__(256) void k_kq(
    const float* __restrict__ Wk, const float* __restrict__ bq,
    const float* __restrict__ bk)
{
    __shared__ float sq[Pp];
    __shared__ float sred[8];
    __shared__ float spart[2][128];
    const int b = blockIdx.y, tid = threadIdx.x;
    const int el = tid & 127, half = tid >> 7;
    const int e = blockIdx.x * 128 + el;

    // sq[p] = bq[p] + sum of 16 partials  (one thread per p)
    {
        const int p = tid;
        float s = bq[p];
#pragma unroll
        for (int c = 0; c < ECH; c++) s += g_qpart[(b * ECH + c) * Pp + p];
        sq[p] = s;
    }
    __syncthreads();

    if (blockIdx.x == 0) {
        float r = bk[tid] * sq[tid];
#pragma unroll
        for (int o = 16; o; o >>= 1) r += __shfl_xor_sync(0xffffffffu, r, o);
        if ((tid & 31) == 0) sred[tid >> 5] = r;
    }
    __syncthreads();
    if (blockIdx.x == 0 && tid == 0) {
        float s = 0.f;
#pragma unroll
        for (int i = 0; i < 8; i++) s += sred[i];
        g_bkq[b] = s;
    }

    // each thread: 128-term partial dot over its p-half (float4 stream)
    {
        const int p_base = half * 128;
        const float4* w4 = (const float4*)(Wk + (size_t)e * Pp + p_base);
        float a0 = 0.f, a1 = 0.f, a2 = 0.f, a3 = 0.f;
#pragma unroll
        for (int p4 = 0; p4 < 32; p4 += 8) {
            float4 w[8];
#pragma unroll
            for (int j = 0; j < 8; j++) w[j] = w4[p4 + j];
#pragma unroll
            for (int j = 0; j < 8; j++) {
                a0 = fmaf(w[j].x, sq[p_base + 4 * (p4 + j) + 0], a0);
                a1 = fmaf(w[j].y, sq[p_base + 4 * (p4 + j) + 1], a1);
                a2 = fmaf(w[j].z, sq[p_base + 4 * (p4 + j) + 2], a2);
                a3 = fmaf(w[j].w, sq[p_base + 4 * (p4 + j) + 3], a3);
            }
        }
        spart[half][el] = (a0 + a1) + (a2 + a3);
    }
    __syncthreads();
    if (half == 0)
        g_kq[b * Hh + e] = spart[0][el] + spart[1][el];
}

// ---------------------------------------------------------------------------
// K3: streaming pass (256 MB). UNCHANGED from R11 (measured 74.1 best).
// ---------------------------------------------------------------------------
__global__ __launch_bounds__(256, 2) void k_stream(const float* __restrict__ enc)
{
    __shared__ float sacc[8][Hh];
    __shared__ float sZ[8];

    const int lane = threadIdx.x & 31;
    const int warp = threadIdx.x >> 5;
    const int b     = blockIdx.x >> 2;
    const int chunk = blockIdx.x & 3;
    const int t0    = chunk * (Tt / CHUNKS) + warp * 64;

    const float4* kq4 = (const float4*)(g_kq + (size_t)b * Hh);
    const float4 k0 = kq4[lane], k1 = kq4[32 + lane],
                 k2 = kq4[64 + lane], k3 = kq4[96 + lane];
    const float bkq = g_bkq[b];

    float4 a0 = {0.f, 0.f, 0.f, 0.f}, a1 = a0, a2 = a0, a3 = a0;
    float Z = 0.f;

#pragma unroll
    for (int grp = 0; grp < 2; grp++) {
        const float4* base =
            (const float4*)(enc + ((size_t)b * Tt + t0 + grp * 32) * Hh);
        float myS = 0.f;

#pragma unroll 1
        for (int i = 0; i < 8; i++) {      // 4 rows per iteration
            const float4* rA = base + (size_t)(4 * i)     * (Hh / 4);
            const float4* rB = base + (size_t)(4 * i + 1) * (Hh / 4);
            const float4* rC = base + (size_t)(4 * i + 2) * (Hh / 4);
            const float4* rD = base + (size_t)(4 * i + 3) * (Hh / 4);
            float4 uA0 = rA[lane], uA1 = rA[32 + lane],
                   uA2 = rA[64 + lane], uA3 = rA[96 + lane];
            float4 uB0 = rB[lane], uB1 = rB[32 + lane],
                   uB2 = rB[64 + lane], uB3 = rB[96 + lane];
            float4 uC0 = rC[lane], uC1 = rC[32 + lane],
                   uC2 = rC[64 + lane], uC3 = rC[96 + lane];
            float4 uD0 = rD[lane], uD1 = rD[32 + lane],
                   uD2 = rD[64 + lane], uD3 = rD[96 + lane];

            float dA = dot16(uA0, uA1, uA2, uA3, k0, k1, k2, k3);
            float dB = dot16(uB0, uB1, uB2, uB3, k0, k1, k2, k3);
            float dC = dot16(uC0, uC1, uC2, uC3, k0, k1, k2, k3);
            float dD = dot16(uD0, uD1, uD2, uD3, k0, k1, k2, k3);

            dA += __shfl_xor_sync(0xffffffffu, dA, 16);
            dB += __shfl_xor_sync(0xffffffffu, dB, 16);
            dC += __shfl_xor_sync(0xffffffffu, dC, 16);
            dD += __shfl_xor_sync(0xffffffffu, dD, 16);
            dA += __shfl_xor_sync(0xffffffffu, dA, 8);
            dB += __shfl_xor_sync(0xffffffffu, dB, 8);
            dC += __shfl_xor_sync(0xffffffffu, dC, 8);
            dD += __shfl_xor_sync(0xffffffffu, dD, 8);
            dA += __shfl_xor_sync(0xffffffffu, dA, 4);
            dB += __shfl_xor_sync(0xffffffffu, dB, 4);
            dC += __shfl_xor_sync(0xffffffffu, dC, 4);
            dD += __shfl_xor_sync(0xffffffffu, dD, 4);
            dA += __shfl_xor_sync(0xffffffffu, dA, 2);
            dB += __shfl_xor_sync(0xffffffffu, dB, 2);
            dC += __shfl_xor_sync(0xffffffffu, dC, 2);
            dD += __shfl_xor_sync(0xffffffffu, dD, 2);
            dA += __shfl_xor_sync(0xffffffffu, dA, 1);
            dB += __shfl_xor_sync(0xffffffffu, dB, 1);
            dC += __shfl_xor_sync(0xffffffffu, dC, 1);
            dD += __shfl_xor_sync(0xffffffffu, dD, 1);

            const float sA = dA + bkq, sB = dB + bkq;
            const float sC = dC + bkq, sD = dD + bkq;
            if (lane == 4 * i)     myS = sA;
            if (lane == 4 * i + 1) myS = sB;
            if (lane == 4 * i + 2) myS = sC;
            if (lane == 4 * i + 3) myS = sD;

            const float wA = fexp2(sA * LOG2E), wB = fexp2(sB * LOG2E);
            const float wC = fexp2(sC * LOG2E), wD = fexp2(sD * LOG2E);
            Z += (wA + wB) + (wC + wD);

            a0.x = fmaf(wA, uA0.x, fmaf(wB, uB0.x, fmaf(wC, uC0.x, fmaf(wD, uD0.x, a0.x))));
            a0.y = fmaf(wA, uA0.y, fmaf(wB, uB0.y, fmaf(wC, uC0.y, fmaf(wD, uD0.y, a0.y))));
            a0.z = fmaf(wA, uA0.z, fmaf(wB, uB0.z, fmaf(wC, uC0.z, fmaf(wD, uD0.z, a0.z))));
            a0.w = fmaf(wA, uA0.w, fmaf(wB, uB0.w, fmaf(wC, uC0.w, fmaf(wD, uD0.w, a0.w))));
            a1.x = fmaf(wA, uA1.x, fmaf(wB, uB1.x, fmaf(wC, uC1.x, fmaf(wD, uD1.x, a1.x))));
            a1.y = fmaf(wA, uA1.y, fmaf(wB, uB1.y, fmaf(wC, uC1.y, fmaf(wD, uD1.y, a1.y))));
            a1.z = fmaf(wA, uA1.z, fmaf(wB, uB1.z, fmaf(wC, uC1.z, fmaf(wD, uD1.z, a1.z))));
            a1.w = fmaf(wA, uA1.w, fmaf(wB, uB1.w, fmaf(wC, uC1.w, fmaf(wD, uD1.w, a1.w))));
            a2.x = fmaf(wA, uA2.x, fmaf(wB, uB2.x, fmaf(wC, uC2.x, fmaf(wD, uD2.x, a2.x))));
            a2.y = fmaf(wA, uA2.y, fmaf(wB, uB2.y, fmaf(wC, uC2.y, fmaf(wD, uD2.y, a2.y))));
            a2.z = fmaf(wA, uA2.z, fmaf(wB, uB2.z, fmaf(wC, uC2.z, fmaf(wD, uD2.z, a2.z))));
            a2.w = fmaf(wA, uA2.w, fmaf(wB, uB2.w, fmaf(wC, uC2.w, fmaf(wD, uD2.w, a2.w))));
            a3.x = fmaf(wA, uA3.x, fmaf(wB, uB3.x, fmaf(wC, uC3.x, fmaf(wD, uD3.x, a3.x))));
            a3.y = fmaf(wA, uA3.y, fmaf(wB, uB3.y, fmaf(wC, uC3.y, fmaf(wD, uD3.y, a3.y))));
            a3.z = fmaf(wA, uA3.z, fmaf(wB, uB3.z, fmaf(wC, uC3.z, fmaf(wD, uD3.z, a3.z))));
            a3.w = fmaf(wA, uA3.w, fmaf(wB, uB3.w, fmaf(wC, uC3.w, fmaf(wD, uD3.w, a3.w))));
        }
        g_raw[b * Tt + t0 + grp * 32 + lane] = myS;
    }

    float4* sa = (float4*)sacc[warp];
    sa[lane] = a0; sa[32 + lane] = a1; sa[64 + lane] = a2; sa[96 + lane] = a3;
    if (lane == 0) sZ[warp] = Z;
    __syncthreads();

    const int pid = blockIdx.x;
    if (threadIdx.x < 128) {
        float4 s = {0.f, 0.f, 0.f, 0.f};
#pragma unroll
        for (int w = 0; w < 8; w++) {
            float4 v = ((const float4*)sacc[w])[threadIdx.x];
            s.x += v.x; s.y += v.y; s.z += v.z; s.w += v.w;
        }
        ((float4*)(g_pacc + (size_t)pid * Hh))[threadIdx.x] = s;
    } else if (threadIdx.x == 128) {
        float z = 0.f;
#pragma unroll
        for (int w = 0; w < 8; w++) z += sZ[w];
        g_pz[pid] = z;
    }
}

// ---------------------------------------------------------------------------
// K4 (fused): attn segment + ctx@Wv partial. grid (16 e-chunks, 64 b) x 256.
// Chunk ec covers attn t in [ec*128, ec*128+128) and e in [ec*32, ec*32+32).
// ---------------------------------------------------------------------------
__global__ __launch_bounds__(256) void k_cpart(
    const float* __restrict__ Wv, float* __restrict__ out)
{
    __shared__ float ssctx[32];
    const int ec = blockIdx.x, b = blockIdx.y, p = threadIdx.x;
    const int e0 = ec * 32;

    float Z = 0.f;
#pragma unroll
    for (int i = 0; i < CHUNKS; i++) Z += g_pz[b * CHUNKS + i];
    const float invZ = 1.f / Z;

    // attn epilogue: 128 t's per block
    if (p < 128) {
        const int t = ec * 128 + p;
        out[Bb * Pp + b * Tt + t] = fexp2(g_raw[b * Tt + t] * LOG2E) * invZ;
    }

    if (p < 32) {
        const int e = e0 + p;
        float s = 0.f;
#pragma unroll
        for (int c = 0; c < CHUNKS; c++)
            s += g_pacc[(size_t)(b * CHUNKS + c) * Hh + e];
        ssctx[p] = s * invZ;
    }
    __syncthreads();

    float a0 = 0.f, a1 = 0.f, a2 = 0.f, a3 = 0.f;
#pragma unroll
    for (int j0 = 0; j0 < 32; j0 += 16) {
        float w[16];
#pragma unroll
        for (int j = 0; j < 16; j++) w[j] = Wv[(e0 + j0 + j) * Pp + p];
#pragma unroll
        for (int j = 0; j < 16; j += 4) {
            a0 = fmaf(ssctx[j0 + j + 0], w[j + 0], a0);
            a1 = fmaf(ssctx[j0 + j + 1], w[j + 1], a1);
            a2 = fmaf(ssctx[j0 + j + 2], w[j + 2], a2);
            a3 = fmaf(ssctx[j0 + j + 3], w[j + 3], a3);
        }
    }
    g_cpart[(b * ECH + ec) * Pp + p] = (a0 + a1) + (a2 + a3);
}

// ---------------------------------------------------------------------------
// K5: context = sum 16 partials + bv.  grid 64 x 256.
// ---------------------------------------------------------------------------
__global__ __launch_bounds__(256) void k_csum(
    const float* __restrict__ bv, float* __restrict__ out)
{
    const int b = blockIdx.x, p = threadIdx.x;
    float c = bv[p];
#pragma unroll
    for (int i = 0; i < ECH; i++) c += g_cpart[(b * ECH + i) * Pp + p];
    out[b * Pp + p] = c;
}

// ---------------------------------------------------------------------------
extern "C" void kernel_launch(void* const* d_in, const int* in_sizes, int n_in,
                              void* d_out, int out_size)
{
    const float* dec = (const float*)d_in[0];
    const float* enc = (const float*)d_in[1];
    const float* Wk  = (const float*)d_in[3];
    const float* bk  = (const float*)d_in[4];
    const float* Wv  = (const float*)d_in[5];
    const float* bv  = (const float*)d_in[6];
    const float* Wq  = (const float*)d_in[7];
    const float* bq  = (const float*)d_in[8];
    float* out = (float*)d_out;

    k_qpart<<<dim3(ECH, Bb), 256>>>(dec, Wq);
    k_kq<<<dim3(4, Bb), 256>>>(Wk, bq, bk);
    k_stream<<<Bb * CHUNKS, 256>>>(enc);
    k_cpart<<<dim3(ECH, Bb), 256>>>(Wv, out);
    k_csum<<<Bb, 256>>>(bv, out);
}